// round 1
// baseline (speedup 1.0000x reference)
#include <cuda_runtime.h>
#include <cstdint>
#include <cstddef>

// ---------------- problem constants ----------------
#define Bb   16
#define Ss   512
#define Ll   12
#define Hh   12
#define DHh  64
#define Dd   768
#define Mm   13      // L + 1
#define PH   144     // L*H
#define GM   8192    // B*S
#define GK   9216    // L*H*DH
#define GN   768     // D

// ---------------- GEMM tiling ----------------
#define BM   128
#define BN   128
#define BK   32
#define KIT  (GK / BK)          // 288
#define SMEM_A_WORDS 4096       // BM*BK
#define SMEM_B_WORDS 4096       // BK*BN
#define GEMM_SMEM_BYTES (2 * (SMEM_A_WORDS + SMEM_B_WORDS) * 4)  // 64 KiB dynamic

__device__ float g_bias[Bb * Dd];   // per-batch bias vector (scratch)

// -------------------------------------------------------------------------
// Kernel 1: bias[b][d] = sum_m (1-mlp_mask)*modal_mlp
//                      + sum_ph (1-attn_mask)*modal_attention + sum_p post_bias
// -------------------------------------------------------------------------
__global__ void bias_kernel(const float* __restrict__ mlp_mask,
                            const float* __restrict__ attn_mask,
                            const float* __restrict__ modal_mlp,
                            const float* __restrict__ modal_attention,
                            const float* __restrict__ post_bias) {
    int b = blockIdx.x;
    int d = threadIdx.x;
    float acc = 0.f;
#pragma unroll
    for (int m = 0; m < Mm; m++)
        acc += (1.f - mlp_mask[b * Mm + m]) * modal_mlp[m * Dd + d];
    for (int ph = 0; ph < PH; ph++)
        acc += (1.f - attn_mask[b * PH + ph]) * modal_attention[ph * Dd + d];
#pragma unroll
    for (int p = 0; p < Ll; p++)
        acc += post_bias[p * Dd + d];
    g_bias[b * Dd + d] = acc;
}

// -------------------------------------------------------------------------
// Kernel 2: out[b,s,d] = sum_m mlp_mask[b,m]*mlp_stack[b,s,m,d] + bias[b,d]
// One block per (b,s) row; 192 threads x float4 = 768 floats.
// -------------------------------------------------------------------------
__global__ void __launch_bounds__(192)
mlp_kernel(const float* __restrict__ mlp_stack,
           const float* __restrict__ mlp_mask,
           float* __restrict__ out) {
    int bs = blockIdx.x;            // 0..8191
    int b  = bs >> 9;               // /512
    int t  = threadIdx.x;           // 0..191
    const float4* mp =
        reinterpret_cast<const float4*>(mlp_stack) + (size_t)bs * Mm * (Dd / 4);
    float4 acc = reinterpret_cast<const float4*>(g_bias)[b * (Dd / 4) + t];
#pragma unroll
    for (int m = 0; m < Mm; m++) {
        float w  = __ldg(&mlp_mask[b * Mm + m]);
        float4 v = mp[m * (Dd / 4) + t];
        acc.x += w * v.x; acc.y += w * v.y;
        acc.z += w * v.z; acc.w += w * v.w;
    }
    reinterpret_cast<float4*>(out)[(size_t)bs * (Dd / 4) + t] = acc;
}

// -------------------------------------------------------------------------
// Kernel 3: out += (mask-scaled attn_stack) @ W_O   — tf32 mma.sync GEMM
//   A[8192][9216] (attn_stack flattened, scaled by attn_mask[b, k/64])
//   B[9216][768]  (W_O flattened)
// Fragment-permuted SMEM: all LDS are conflict-free LDS.128 / LDS.64.
// -------------------------------------------------------------------------
__device__ __forceinline__ uint32_t f2tf(float x) {
    uint32_t u;
    asm("cvt.rna.tf32.f32 %0, %1;" : "=r"(u) : "f"(x));
    return u;
}

__device__ __forceinline__ void mma_tf32(float* c, const uint4& a, const uint2& b) {
    asm volatile(
        "mma.sync.aligned.m16n8k8.row.col.f32.tf32.tf32.f32 "
        "{%0,%1,%2,%3}, {%4,%5,%6,%7}, {%8,%9}, {%0,%1,%2,%3};"
        : "+f"(c[0]), "+f"(c[1]), "+f"(c[2]), "+f"(c[3])
        : "r"(a.x), "r"(a.y), "r"(a.z), "r"(a.w), "r"(b.x), "r"(b.y));
}

__global__ void __launch_bounds__(256, 1)
attn_gemm_kernel(const float* __restrict__ A,         // [GM][GK]
                 const float* __restrict__ Wo,        // [GK][GN]
                 const float* __restrict__ attn_mask, // [Bb][PH]
                 float* __restrict__ out)             // [GM][GN]
{
    extern __shared__ float smem[];
    float* sA = smem;                        // [2][SMEM_A_WORDS]
    float* sB = smem + 2 * SMEM_A_WORDS;     // [2][SMEM_B_WORDS]
    __shared__ float sMask[PH];

    const int t      = threadIdx.x;
    const int w      = t >> 5;
    const int lane   = t & 31;
    const int warp_m = w >> 2;               // 0..1
    const int warp_n = w & 3;                // 0..3
    const int mRow0  = blockIdx.y * BM;
    const int nCol0  = blockIdx.x * BN;
    const int b      = mRow0 >> 9;           // batch of this M-tile (BM|512)

    if (t < PH) sMask[t] = attn_mask[b * PH + t];
    __syncthreads();

    const int gq = lane >> 2;                // groupID
    const int c4 = lane & 3;                 // threadID_in_group

    // ---- per-thread load-group invariants ----
    // A: 32 fragment-groups (ks in 0..3, mtile in 0..7); each thread owns 4.
    const float* pA[4]; int sAoff[4];
#pragma unroll
    for (int i = 0; i < 4; i++) {
        int gA = w * 4 + i;
        int ks = gA >> 3, mt = gA & 7;
        int row = mRow0 + mt * 16 + gq;
        pA[i]    = A + (size_t)row * GK + ks * 8 + c4;
        sAoff[i] = gA * 128 + lane * 4;
    }
    // B: 64 fragment-groups (ks in 0..3, ntile in 0..15); each thread owns 8.
    const float* pB[8]; int sBoff[8];
#pragma unroll
    for (int j = 0; j < 8; j++) {
        int gB = w * 8 + j;
        int ks = gB >> 4, nt = gB & 15;
        int col = nCol0 + nt * 8 + gq;       // n within 8x8: lane>>2
        pB[j]    = Wo + (size_t)(ks * 8 + c4) * GN + col;  // k within: lane&3
        sBoff[j] = gB * 64 + lane * 2;
    }

    float ra[16], rb[16];

    auto loadAB = [&](int kt) {
        size_t ao = (size_t)kt * BK;
#pragma unroll
        for (int i = 0; i < 4; i++) {
            const float* p = pA[i] + ao;
            ra[4 * i + 0] = __ldg(p);
            ra[4 * i + 1] = __ldg(p + (size_t)8 * GK);
            ra[4 * i + 2] = __ldg(p + 4);
            ra[4 * i + 3] = __ldg(p + (size_t)8 * GK + 4);
        }
        size_t bo = (size_t)kt * BK * GN;
#pragma unroll
        for (int j = 0; j < 8; j++) {
            const float* p = pB[j] + bo;
            rb[2 * j + 0] = __ldg(p);
            rb[2 * j + 1] = __ldg(p + 4 * GN);
        }
    };

    auto storeAB = [&](int buf, float s) {
        float* a = sA + buf * SMEM_A_WORDS;
#pragma unroll
        for (int i = 0; i < 4; i++) {
            uint4 v;
            v.x = f2tf(ra[4 * i + 0] * s);
            v.y = f2tf(ra[4 * i + 1] * s);
            v.z = f2tf(ra[4 * i + 2] * s);
            v.w = f2tf(ra[4 * i + 3] * s);
            *reinterpret_cast<uint4*>(a + sAoff[i]) = v;
        }
        float* bbuf = sB + buf * SMEM_B_WORDS;
#pragma unroll
        for (int j = 0; j < 8; j++) {
            uint2 v;
            v.x = f2tf(rb[2 * j + 0]);
            v.y = f2tf(rb[2 * j + 1]);
            *reinterpret_cast<uint2*>(bbuf + sBoff[j]) = v;
        }
    };

    float acc[4][4][4];
#pragma unroll
    for (int mt = 0; mt < 4; mt++)
#pragma unroll
        for (int nt = 0; nt < 4; nt++)
#pragma unroll
            for (int r = 0; r < 4; r++) acc[mt][nt][r] = 0.f;

    // prologue
    loadAB(0);
    storeAB(0, sMask[0]);
    __syncthreads();

    for (int kt = 0; kt < KIT; kt++) {
        int cur = kt & 1;
        if (kt + 1 < KIT) loadAB(kt + 1);

        const float* a    = sA + cur * SMEM_A_WORDS;
        const float* bbuf = sB + cur * SMEM_B_WORDS;
#pragma unroll
        for (int ks = 0; ks < 4; ks++) {
            uint4 af[4]; uint2 bf[4];
#pragma unroll
            for (int mt = 0; mt < 4; mt++)
                af[mt] = *reinterpret_cast<const uint4*>(
                    a + (ks * 8 + warp_m * 4 + mt) * 128 + lane * 4);
#pragma unroll
            for (int nt = 0; nt < 4; nt++)
                bf[nt] = *reinterpret_cast<const uint2*>(
                    bbuf + (ks * 16 + warp_n * 4 + nt) * 64 + lane * 2);
#pragma unroll
            for (int mt = 0; mt < 4; mt++)
#pragma unroll
                for (int nt = 0; nt < 4; nt++)
                    mma_tf32(acc[mt][nt], af[mt], bf[nt]);
        }

        if (kt + 1 < KIT) storeAB(cur ^ 1, sMask[(kt + 1) >> 1]);
        __syncthreads();
    }

    // epilogue: out += acc (each element owned by exactly one thread)
#pragma unroll
    for (int mt = 0; mt < 4; mt++) {
        int r0 = mRow0 + warp_m * 64 + mt * 16 + gq;
#pragma unroll
        for (int nt = 0; nt < 4; nt++) {
            int col = nCol0 + warp_n * 32 + nt * 8 + c4 * 2;
            float2* p0 = reinterpret_cast<float2*>(out + (size_t)r0 * GN + col);
            float2 v0 = *p0;
            v0.x += acc[mt][nt][0]; v0.y += acc[mt][nt][1];
            *p0 = v0;
            float2* p1 = reinterpret_cast<float2*>(out + (size_t)(r0 + 8) * GN + col);
            float2 v1 = *p1;
            v1.x += acc[mt][nt][2]; v1.y += acc[mt][nt][3];
            *p1 = v1;
        }
    }
}

// -------------------------------------------------------------------------
// launch
// -------------------------------------------------------------------------
static const float* find_in(void* const* d_in, const int* in_sizes, int n_in,
                            long long want) {
    for (int i = 0; i < n_in; i++)
        if ((long long)in_sizes[i] == want) return (const float*)d_in[i];
    return nullptr;
}

extern "C" void kernel_launch(void* const* d_in, const int* in_sizes, int n_in,
                              void* d_out, int out_size) {
    // identify inputs by element count (all distinct)
    const float* mlp_stack       = find_in(d_in, in_sizes, n_in, (long long)Bb * Ss * Mm * Dd);
    const float* attn_stack      = find_in(d_in, in_sizes, n_in, (long long)Bb * Ss * Ll * Hh * DHh);
    const float* mlp_mask        = find_in(d_in, in_sizes, n_in, (long long)Bb * Mm);
    const float* attn_mask       = find_in(d_in, in_sizes, n_in, (long long)Bb * Ll * Hh);
    const float* modal_mlp       = find_in(d_in, in_sizes, n_in, (long long)Mm * Dd);
    const float* modal_attention = find_in(d_in, in_sizes, n_in, (long long)Ll * Hh * Dd);
    const float* W_O             = find_in(d_in, in_sizes, n_in, (long long)Ll * Hh * DHh * Dd);
    const float* post_bias       = find_in(d_in, in_sizes, n_in, (long long)Ll * Dd);
    float* out = (float*)d_out;

    static bool attr_set = false;
    if (!attr_set) {
        cudaFuncSetAttribute(attn_gemm_kernel,
                             cudaFuncAttributeMaxDynamicSharedMemorySize,
                             GEMM_SMEM_BYTES);
        attr_set = true;
    }

    bias_kernel<<<Bb, Dd>>>(mlp_mask, attn_mask, modal_mlp, modal_attention,
                            post_bias);
    mlp_kernel<<<GM, Dd / 4>>>(mlp_stack, mlp_mask, out);
    dim3 grid(GN / BN, GM / BM);   // (6, 64)
    attn_gemm_kernel<<<grid, 256, GEMM_SMEM_BYTES>>>(attn_stack, W_O, attn_mask,
                                                     out);
}

// round 3
// speedup vs baseline: 2.8316x; 2.8316x over previous
#include <cuda_runtime.h>
#include <cuda_fp16.h>
#include <cstdint>
#include <cstddef>

// ---------------- problem constants ----------------
#define Bb   16
#define Ss   512
#define Ll   12
#define Hh   12
#define DHh  64
#define Dd   768
#define Mm   13
#define PH   144
#define GM   8192
#define GK   9216
#define GN   768

// ---------------- GEMM tiling ----------------
#define BM   128
#define BN   128
#define BK   64
#define KIT  (GK / BK)           // 144
#define STAGES 4
#define LDA_H 72                 // halfs per A smem row (64 + 8 pad)
#define LDB_H 136                // halfs per B smem row (128 + 8 pad)
#define SA_BYTES (BM * LDA_H * 2)        // 18432
#define SB_BYTES (BK * LDB_H * 2)        // 17408
#define STAGE_BYTES (SA_BYTES + SB_BYTES) // 35840
#define GEMM_DSMEM (STAGES * STAGE_BYTES) // 143360

__device__ __half g_Ah[(size_t)GM * GK];   // mask-scaled fp16 A
__device__ __half g_Wh[(size_t)GK * GN];   // fp16 W_O (row-major [K][N])
__device__ float  g_bias[Bb * Dd];

// ============================ PTX helpers ============================
__device__ __forceinline__ uint32_t smem_u32(const void* p) {
    uint32_t a;
    asm("{ .reg .u64 t; cvta.to.shared.u64 t, %1; cvt.u32.u64 %0, t; }"
        : "=r"(a) : "l"(p));
    return a;
}
__device__ __forceinline__ void cpasync16(uint32_t dst, const void* src) {
    asm volatile("cp.async.cg.shared.global [%0], [%1], 16;"
                 :: "r"(dst), "l"(src));
}
__device__ __forceinline__ void cp_commit() {
    asm volatile("cp.async.commit_group;");
}
__device__ __forceinline__ void cp_wait2() {
    asm volatile("cp.async.wait_group 2;");
}
__device__ __forceinline__ void ldsm4(uint32_t* r, uint32_t addr) {
    asm volatile("ldmatrix.sync.aligned.m8n8.x4.shared.b16 {%0,%1,%2,%3}, [%4];"
                 : "=r"(r[0]), "=r"(r[1]), "=r"(r[2]), "=r"(r[3]) : "r"(addr));
}
__device__ __forceinline__ void ldsm4t(uint32_t* r, uint32_t addr) {
    asm volatile("ldmatrix.sync.aligned.m8n8.x4.trans.shared.b16 {%0,%1,%2,%3}, [%4];"
                 : "=r"(r[0]), "=r"(r[1]), "=r"(r[2]), "=r"(r[3]) : "r"(addr));
}
__device__ __forceinline__ void mma16816(float* c, const uint32_t* a,
                                         uint32_t b0, uint32_t b1) {
    asm volatile(
        "mma.sync.aligned.m16n8k16.row.col.f32.f16.f16.f32 "
        "{%0,%1,%2,%3}, {%4,%5,%6,%7}, {%8,%9}, {%0,%1,%2,%3};"
        : "+f"(c[0]), "+f"(c[1]), "+f"(c[2]), "+f"(c[3])
        : "r"(a[0]), "r"(a[1]), "r"(a[2]), "r"(a[3]), "r"(b0), "r"(b1));
}

// ============================ Kernel 1: bias ============================
__global__ void bias_kernel(const float* __restrict__ mlp_mask,
                            const float* __restrict__ attn_mask,
                            const float* __restrict__ modal_mlp,
                            const float* __restrict__ modal_attention,
                            const float* __restrict__ post_bias) {
    int b = blockIdx.x;
    int d = threadIdx.x;
    float acc = 0.f;
#pragma unroll
    for (int m = 0; m < Mm; m++)
        acc += (1.f - mlp_mask[b * Mm + m]) * modal_mlp[m * Dd + d];
    for (int ph = 0; ph < PH; ph++)
        acc += (1.f - attn_mask[b * PH + ph]) * modal_attention[ph * Dd + d];
#pragma unroll
    for (int p = 0; p < Ll; p++)
        acc += post_bias[p * Dd + d];
    g_bias[b * Dd + d] = acc;
}

// ============================ Kernel 2: W_O -> fp16 ============================
__global__ void __launch_bounds__(256)
prep_w(const float* __restrict__ Wo) {
    size_t i = (size_t)blockIdx.x * 256 + threadIdx.x;  // float4 idx, 1769472 total
    float4 v = reinterpret_cast<const float4*>(Wo)[i];
    __half2* dst = reinterpret_cast<__half2*>(g_Wh);
    dst[i * 2]     = __floats2half2_rn(v.x, v.y);
    dst[i * 2 + 1] = __floats2half2_rn(v.z, v.w);
}

// ============================ Kernel 3: A mask-scale -> fp16 ============================
__global__ void __launch_bounds__(256)
prep_a(const float* __restrict__ attn_stack, const float* __restrict__ attn_mask) {
    __shared__ float sM[PH];
    int bs = blockIdx.x;
    int b  = bs >> 9;
    int t  = threadIdx.x;
    if (t < PH) sM[t] = attn_mask[b * PH + t];
    __syncthreads();
    const float4* src = reinterpret_cast<const float4*>(attn_stack + (size_t)bs * GK);
    __half2* dst = reinterpret_cast<__half2*>(g_Ah + (size_t)bs * GK);
#pragma unroll
    for (int i = 0; i < 9; i++) {
        int idx = t + 256 * i;            // 0..2303 float4 units
        float s = sM[idx >> 4];           // 16 float4 = 64 floats per head
        float4 v = src[idx];
        dst[idx * 2]     = __floats2half2_rn(v.x * s, v.y * s);
        dst[idx * 2 + 1] = __floats2half2_rn(v.z * s, v.w * s);
    }
}

// ============================ Kernel 4: mlp term ============================
__global__ void __launch_bounds__(192)
mlp_kernel(const float* __restrict__ mlp_stack,
           const float* __restrict__ mlp_mask,
           float* __restrict__ out) {
    int bs = blockIdx.x;
    int b  = bs >> 9;
    int t  = threadIdx.x;
    const float4* mp =
        reinterpret_cast<const float4*>(mlp_stack) + (size_t)bs * Mm * (Dd / 4);
    float4 acc = reinterpret_cast<const float4*>(g_bias)[b * (Dd / 4) + t];
#pragma unroll
    for (int m = 0; m < Mm; m++) {
        float w  = __ldg(&mlp_mask[b * Mm + m]);
        float4 v = mp[m * (Dd / 4) + t];
        acc.x += w * v.x; acc.y += w * v.y;
        acc.z += w * v.z; acc.w += w * v.w;
    }
    reinterpret_cast<float4*>(out)[(size_t)bs * (Dd / 4) + t] = acc;
}

// ============================ Kernel 5: fp16 mma.sync GEMM ============================
// out[M,N] += g_Ah[M,K] @ g_Wh[K,N]
__global__ void __launch_bounds__(256, 1)
attn_gemm(float* __restrict__ out) {
    extern __shared__ char smem[];
    const uint32_t s0 = smem_u32(smem);

    const int t    = threadIdx.x;
    const int lane = t & 31;
    const int wid  = t >> 5;
    const int wm   = wid >> 2;       // 0..1
    const int wn   = wid & 3;        // 0..3
    const int mRow0 = blockIdx.y * BM;
    const int nCol0 = blockIdx.x * BN;

    // ---- cp.async thread-invariant bases ----
    const __half* gA = g_Ah + (size_t)(mRow0 + (t >> 3)) * GK + (t & 7) * 8;
    const uint32_t sAw = s0 + (t >> 3) * (LDA_H * 2) + (t & 7) * 16;
    const __half* gB = g_Wh + (size_t)(t >> 4) * GN + nCol0 + (t & 15) * 8;
    const uint32_t sBw = s0 + SA_BYTES + (t >> 4) * (LDB_H * 2) + (t & 15) * 16;

    auto load_stage = [&](int kt, int st) {
        uint32_t so = st * STAGE_BYTES;
        const __half* ga = gA + kt * BK;
#pragma unroll
        for (int i = 0; i < 4; i++)
            cpasync16(sAw + so + i * 32 * (LDA_H * 2), ga + (size_t)i * 32 * GK);
        const __half* gb = gB + (size_t)kt * BK * GN;
#pragma unroll
        for (int i = 0; i < 4; i++)
            cpasync16(sBw + so + i * 16 * (LDB_H * 2), gb + (size_t)i * 16 * GN);
        cp_commit();
    };

    // ---- ldmatrix bases ----
    // A: row = wm*64 + mi*16 + (lane&15); col halfs = ks*16 + (lane>>4)*8
    const uint32_t aBase = s0 + (wm * 64 + (lane & 15)) * (LDA_H * 2) + (lane >> 4) * 16;
    // B: row = ks*16 + (lane&15); col halfs = wn*32 + nj*16 + (lane>>4)*8
    const uint32_t bBase = s0 + SA_BYTES + (lane & 15) * (LDB_H * 2) + wn * 64 + (lane >> 4) * 16;

    float acc[4][4][4];
#pragma unroll
    for (int mi = 0; mi < 4; mi++)
#pragma unroll
        for (int nt = 0; nt < 4; nt++)
#pragma unroll
            for (int r = 0; r < 4; r++) acc[mi][nt][r] = 0.f;

    load_stage(0, 0);
    load_stage(1, 1);
    load_stage(2, 2);

    for (int kt = 0; kt < KIT; kt++) {
        cp_wait2();
        __syncthreads();
        if (kt + 3 < KIT) load_stage(kt + 3, (kt + 3) & 3);
        else cp_commit();   // keep group-count semantics for wait_group 2

        const uint32_t so = (kt & 3) * STAGE_BYTES;
#pragma unroll
        for (int ks = 0; ks < 4; ks++) {
            uint32_t af[4][4];
#pragma unroll
            for (int mi = 0; mi < 4; mi++)
                ldsm4(af[mi], aBase + so + mi * 16 * (LDA_H * 2) + ks * 32);
            uint32_t bf[2][4];
#pragma unroll
            for (int nj = 0; nj < 2; nj++)
                ldsm4t(bf[nj], bBase + so + ks * 16 * (LDB_H * 2) + nj * 32);
#pragma unroll
            for (int mi = 0; mi < 4; mi++)
#pragma unroll
                for (int nt = 0; nt < 4; nt++)
                    mma16816(acc[mi][nt], af[mi],
                             bf[nt >> 1][(nt & 1) * 2], bf[nt >> 1][(nt & 1) * 2 + 1]);
        }
    }

    // ---- epilogue: out += acc ----
    const int g  = lane >> 2;
    const int tq = lane & 3;
#pragma unroll
    for (int mi = 0; mi < 4; mi++) {
        int row0 = mRow0 + wm * 64 + mi * 16 + g;
#pragma unroll
        for (int nt = 0; nt < 4; nt++) {
            int col = nCol0 + wn * 32 + nt * 8 + tq * 2;
            float2* p0 = reinterpret_cast<float2*>(out + (size_t)row0 * GN + col);
            float2 v0 = *p0;
            v0.x += acc[mi][nt][0]; v0.y += acc[mi][nt][1];
            *p0 = v0;
            float2* p1 = reinterpret_cast<float2*>(out + (size_t)(row0 + 8) * GN + col);
            float2 v1 = *p1;
            v1.x += acc[mi][nt][2]; v1.y += acc[mi][nt][3];
            *p1 = v1;
        }
    }
}

// ============================ launch ============================
static const float* find_in(void* const* d_in, const int* in_sizes, int n_in,
                            long long want) {
    for (int i = 0; i < n_in; i++)
        if ((long long)in_sizes[i] == want) return (const float*)d_in[i];
    return nullptr;
}

extern "C" void kernel_launch(void* const* d_in, const int* in_sizes, int n_in,
                              void* d_out, int out_size) {
    const float* mlp_stack       = find_in(d_in, in_sizes, n_in, (long long)Bb * Ss * Mm * Dd);
    const float* attn_stack      = find_in(d_in, in_sizes, n_in, (long long)Bb * Ss * Ll * Hh * DHh);
    const float* mlp_mask        = find_in(d_in, in_sizes, n_in, (long long)Bb * Mm);
    const float* attn_mask       = find_in(d_in, in_sizes, n_in, (long long)Bb * Ll * Hh);
    const float* modal_mlp       = find_in(d_in, in_sizes, n_in, (long long)Mm * Dd);
    const float* modal_attention = find_in(d_in, in_sizes, n_in, (long long)Ll * Hh * Dd);
    const float* W_O             = find_in(d_in, in_sizes, n_in, (long long)Ll * Hh * DHh * Dd);
    const float* post_bias       = find_in(d_in, in_sizes, n_in, (long long)Ll * Dd);
    float* out = (float*)d_out;

    static bool inited = false;
    if (!inited) {
        cudaFuncSetAttribute(attn_gemm,
                             cudaFuncAttributeMaxDynamicSharedMemorySize, GEMM_DSMEM);
        inited = true;
    }

    bias_kernel<<<Bb, Dd>>>(mlp_mask, attn_mask, modal_mlp, modal_attention,
                            post_bias);
    prep_w<<<(GK * GN / 4) / 256, 256>>>(W_O);
    prep_a<<<GM, 256>>>(attn_stack, attn_mask);
    mlp_kernel<<<GM, Dd / 4>>>(mlp_stack, mlp_mask, out);
    dim3 ggrid(GN / BN, GM / BM);   // (6, 64)
    attn_gemm<<<ggrid, 256, GEMM_DSMEM>>>(out);
}

// round 4
// speedup vs baseline: 3.3055x; 1.1674x over previous
#include <cuda_runtime.h>
#include <cuda_fp16.h>
#include <cstdint>
#include <cstddef>

// ---------------- problem constants ----------------
#define Bb   16
#define Ss   512
#define Ll   12
#define Hh   12
#define DHh  64
#define Dd   768
#define Mm   13
#define PH   144
#define GM   8192
#define GK   9216
#define GN   768

// ---------------- GEMM tiling ----------------
#define BM   128
#define BN   128
#define BK   64
#define KIT  (GK / BK)           // 144
#define STAGES 3
#define LDA_H 72                 // halfs per A smem row (64 + 8 pad)
#define LDB_H 136                // halfs per B smem row (128 + 8 pad)
#define SA_BYTES (BM * LDA_H * 2)        // 18432
#define SB_BYTES (BK * LDB_H * 2)        // 17408
#define STAGE_BYTES (SA_BYTES + SB_BYTES) // 35840
#define GEMM_DSMEM (STAGES * STAGE_BYTES) // 107520 -> 2 CTAs/SM

__device__ __half g_Ah[(size_t)GM * GK];   // mask-scaled fp16 A
__device__ __half g_Wh[(size_t)GK * GN];   // fp16 W_O (row-major [K][N])
__device__ float  g_bias[Bb * Dd];

// ============================ PTX helpers ============================
__device__ __forceinline__ uint32_t smem_u32(const void* p) {
    uint32_t a;
    asm("{ .reg .u64 t; cvta.to.shared.u64 t, %1; cvt.u32.u64 %0, t; }"
        : "=r"(a) : "l"(p));
    return a;
}
__device__ __forceinline__ void cpasync16(uint32_t dst, const void* src) {
    asm volatile("cp.async.cg.shared.global [%0], [%1], 16;"
                 :: "r"(dst), "l"(src));
}
__device__ __forceinline__ void cp_commit() {
    asm volatile("cp.async.commit_group;");
}
__device__ __forceinline__ void cp_wait1() {
    asm volatile("cp.async.wait_group 1;");
}
__device__ __forceinline__ void ldsm4(uint32_t* r, uint32_t addr) {
    asm volatile("ldmatrix.sync.aligned.m8n8.x4.shared.b16 {%0,%1,%2,%3}, [%4];"
                 : "=r"(r[0]), "=r"(r[1]), "=r"(r[2]), "=r"(r[3]) : "r"(addr));
}
__device__ __forceinline__ void ldsm4t(uint32_t* r, uint32_t addr) {
    asm volatile("ldmatrix.sync.aligned.m8n8.x4.trans.shared.b16 {%0,%1,%2,%3}, [%4];"
                 : "=r"(r[0]), "=r"(r[1]), "=r"(r[2]), "=r"(r[3]) : "r"(addr));
}
__device__ __forceinline__ void mma16816(float* c, const uint32_t* a,
                                         uint32_t b0, uint32_t b1) {
    asm volatile(
        "mma.sync.aligned.m16n8k16.row.col.f32.f16.f16.f32 "
        "{%0,%1,%2,%3}, {%4,%5,%6,%7}, {%8,%9}, {%0,%1,%2,%3};"
        : "+f"(c[0]), "+f"(c[1]), "+f"(c[2]), "+f"(c[3])
        : "r"(a[0]), "r"(a[1]), "r"(a[2]), "r"(a[3]), "r"(b0), "r"(b1));
}

// ============================ Kernel 1: bias ============================
__global__ void bias_kernel(const float* __restrict__ mlp_mask,
                            const float* __restrict__ attn_mask,
                            const float* __restrict__ modal_mlp,
                            const float* __restrict__ modal_attention,
                            const float* __restrict__ post_bias) {
    int b = blockIdx.x;
    int d = threadIdx.x;
    float acc = 0.f;
#pragma unroll
    for (int m = 0; m < Mm; m++)
        acc += (1.f - mlp_mask[b * Mm + m]) * modal_mlp[m * Dd + d];
    for (int ph = 0; ph < PH; ph++)
        acc += (1.f - attn_mask[b * PH + ph]) * modal_attention[ph * Dd + d];
#pragma unroll
    for (int p = 0; p < Ll; p++)
        acc += post_bias[p * Dd + d];
    g_bias[b * Dd + d] = acc;
}

// ============================ Kernel 2: W_O -> fp16 ============================
__global__ void __launch_bounds__(256)
prep_w(const float* __restrict__ Wo) {
    size_t i = (size_t)blockIdx.x * 256 + threadIdx.x;  // float4 idx
    float4 v = reinterpret_cast<const float4*>(Wo)[i];
    __half2* dst = reinterpret_cast<__half2*>(g_Wh);
    dst[i * 2]     = __floats2half2_rn(v.x, v.y);
    dst[i * 2 + 1] = __floats2half2_rn(v.z, v.w);
}

// ============================ Kernel 3: A mask-scale -> fp16 ============================
__global__ void __launch_bounds__(256)
prep_a(const float* __restrict__ attn_stack, const float* __restrict__ attn_mask) {
    __shared__ float sM[PH];
    int bs = blockIdx.x;
    int b  = bs >> 9;
    int t  = threadIdx.x;
    if (t < PH) sM[t] = attn_mask[b * PH + t];
    __syncthreads();
    const float4* src = reinterpret_cast<const float4*>(attn_stack + (size_t)bs * GK);
    __half2* dst = reinterpret_cast<__half2*>(g_Ah + (size_t)bs * GK);
#pragma unroll
    for (int i = 0; i < 9; i++) {
        int idx = t + 256 * i;            // 0..2303 float4 units
        float s = sM[idx >> 4];           // 16 float4 = 64 floats per head
        float4 v = src[idx];
        dst[idx * 2]     = __floats2half2_rn(v.x * s, v.y * s);
        dst[idx * 2 + 1] = __floats2half2_rn(v.z * s, v.w * s);
    }
}

// ============================ Kernel 4: mlp term ============================
__global__ void __launch_bounds__(192)
mlp_kernel(const float* __restrict__ mlp_stack,
           const float* __restrict__ mlp_mask,
           float* __restrict__ out) {
    int bs = blockIdx.x;
    int b  = bs >> 9;
    int t  = threadIdx.x;
    const float4* mp =
        reinterpret_cast<const float4*>(mlp_stack) + (size_t)bs * Mm * (Dd / 4);
    float4 acc = reinterpret_cast<const float4*>(g_bias)[b * (Dd / 4) + t];
#pragma unroll
    for (int m = 0; m < Mm; m++) {
        float w  = __ldg(&mlp_mask[b * Mm + m]);
        float4 v = mp[m * (Dd / 4) + t];
        acc.x += w * v.x; acc.y += w * v.y;
        acc.z += w * v.z; acc.w += w * v.w;
    }
    reinterpret_cast<float4*>(out)[(size_t)bs * (Dd / 4) + t] = acc;
}

// ============================ Kernel 5: fp16 mma.sync GEMM ============================
// out[M,N] += g_Ah[M,K] @ g_Wh[K,N]    (2 CTAs/SM)
__global__ void __launch_bounds__(256, 2)
attn_gemm(float* __restrict__ out) {
    extern __shared__ char smem[];
    const uint32_t s0 = smem_u32(smem);

    const int t    = threadIdx.x;
    const int lane = t & 31;
    const int wid  = t >> 5;
    const int wm   = wid >> 2;       // 0..1
    const int wn   = wid & 3;        // 0..3
    const int mRow0 = blockIdx.y * BM;
    const int nCol0 = blockIdx.x * BN;

    // ---- cp.async thread-invariant bases ----
    const __half* gA = g_Ah + (size_t)(mRow0 + (t >> 3)) * GK + (t & 7) * 8;
    const uint32_t sAw = s0 + (t >> 3) * (LDA_H * 2) + (t & 7) * 16;
    const __half* gB = g_Wh + (size_t)(t >> 4) * GN + nCol0 + (t & 15) * 8;
    const uint32_t sBw = s0 + SA_BYTES + (t >> 4) * (LDB_H * 2) + (t & 15) * 16;

    auto load_stage = [&](int kt, int st) {
        uint32_t so = st * STAGE_BYTES;
        const __half* ga = gA + kt * BK;
#pragma unroll
        for (int i = 0; i < 4; i++)
            cpasync16(sAw + so + i * 32 * (LDA_H * 2), ga + (size_t)i * 32 * GK);
        const __half* gb = gB + (size_t)kt * BK * GN;
#pragma unroll
        for (int i = 0; i < 4; i++)
            cpasync16(sBw + so + i * 16 * (LDB_H * 2), gb + (size_t)i * 16 * GN);
        cp_commit();
    };

    // ---- ldmatrix bases ----
    const uint32_t aBase = s0 + (wm * 64 + (lane & 15)) * (LDA_H * 2) + (lane >> 4) * 16;
    const uint32_t bBase = s0 + SA_BYTES + (lane & 15) * (LDB_H * 2) + wn * 64 + (lane >> 4) * 16;

    float acc[4][4][4];
#pragma unroll
    for (int mi = 0; mi < 4; mi++)
#pragma unroll
        for (int nt = 0; nt < 4; nt++)
#pragma unroll
            for (int r = 0; r < 4; r++) acc[mi][nt][r] = 0.f;

    load_stage(0, 0);
    load_stage(1, 1);

    int st_c = 0;  // stage being computed
    int st_l = 2;  // stage to load into
    for (int kt = 0; kt < KIT; kt++) {
        cp_wait1();
        __syncthreads();
        if (kt + 2 < KIT) load_stage(kt + 2, st_l);
        else cp_commit();   // keep group-count semantics for wait_group 1

        const uint32_t so = st_c * STAGE_BYTES;
#pragma unroll
        for (int ks = 0; ks < 4; ks++) {
            uint32_t af[4][4];
#pragma unroll
            for (int mi = 0; mi < 4; mi++)
                ldsm4(af[mi], aBase + so + mi * 16 * (LDA_H * 2) + ks * 32);
            uint32_t bf[2][4];
#pragma unroll
            for (int nj = 0; nj < 2; nj++)
                ldsm4t(bf[nj], bBase + so + ks * 16 * (LDB_H * 2) + nj * 32);
#pragma unroll
            for (int mi = 0; mi < 4; mi++)
#pragma unroll
                for (int nt = 0; nt < 4; nt++)
                    mma16816(acc[mi][nt], af[mi],
                             bf[nt >> 1][(nt & 1) * 2], bf[nt >> 1][(nt & 1) * 2 + 1]);
        }
        st_c = (st_c == STAGES - 1) ? 0 : st_c + 1;
        st_l = (st_l == STAGES - 1) ? 0 : st_l + 1;
    }

    // ---- epilogue: out += acc ----
    const int g  = lane >> 2;
    const int tq = lane & 3;
#pragma unroll
    for (int mi = 0; mi < 4; mi++) {
        int row0 = mRow0 + wm * 64 + mi * 16 + g;
#pragma unroll
        for (int nt = 0; nt < 4; nt++) {
            int col = nCol0 + wn * 32 + nt * 8 + tq * 2;
            float2* p0 = reinterpret_cast<float2*>(out + (size_t)row0 * GN + col);
            float2 v0 = *p0;
            v0.x += acc[mi][nt][0]; v0.y += acc[mi][nt][1];
            *p0 = v0;
            float2* p1 = reinterpret_cast<float2*>(out + (size_t)(row0 + 8) * GN + col);
            float2 v1 = *p1;
            v1.x += acc[mi][nt][2]; v1.y += acc[mi][nt][3];
            *p1 = v1;
        }
    }
}

// ============================ launch ============================
static const float* find_in(void* const* d_in, const int* in_sizes, int n_in,
                            long long want) {
    for (int i = 0; i < n_in; i++)
        if ((long long)in_sizes[i] == want) return (const float*)d_in[i];
    return nullptr;
}

extern "C" void kernel_launch(void* const* d_in, const int* in_sizes, int n_in,
                              void* d_out, int out_size) {
    const float* mlp_stack       = find_in(d_in, in_sizes, n_in, (long long)Bb * Ss * Mm * Dd);
    const float* attn_stack      = find_in(d_in, in_sizes, n_in, (long long)Bb * Ss * Ll * Hh * DHh);
    const float* mlp_mask        = find_in(d_in, in_sizes, n_in, (long long)Bb * Mm);
    const float* attn_mask       = find_in(d_in, in_sizes, n_in, (long long)Bb * Ll * Hh);
    const float* modal_mlp       = find_in(d_in, in_sizes, n_in, (long long)Mm * Dd);
    const float* modal_attention = find_in(d_in, in_sizes, n_in, (long long)Ll * Hh * Dd);
    const float* W_O             = find_in(d_in, in_sizes, n_in, (long long)Ll * Hh * DHh * Dd);
    const float* post_bias       = find_in(d_in, in_sizes, n_in, (long long)Ll * Dd);
    float* out = (float*)d_out;

    static bool inited = false;
    if (!inited) {
        cudaFuncSetAttribute(attn_gemm,
                             cudaFuncAttributeMaxDynamicSharedMemorySize, GEMM_DSMEM);
        inited = true;
    }

    bias_kernel<<<Bb, Dd>>>(mlp_mask, attn_mask, modal_mlp, modal_attention,
                            post_bias);
    prep_w<<<(GK * GN / 4) / 256, 256>>>(W_O);
    prep_a<<<GM, 256>>>(attn_stack, attn_mask);
    mlp_kernel<<<GM, Dd / 4>>>(mlp_stack, mlp_mask, out);
    dim3 ggrid(GN / BN, GM / BM);   // (6, 64)
    attn_gemm<<<ggrid, 256, GEMM_DSMEM>>>(out);
}